// round 2
// baseline (speedup 1.0000x reference)
#include <cuda_runtime.h>
#include <cuda_bf16.h>
#include <cooperative_groups.h>
#include <math.h>

namespace cg = cooperative_groups;

#define B_   64
#define T_   256
#define DIN  128
#define H_   256
#define G3   768

#define OFF_CHOL   131072ull
#define OFF_MEANX  33685504ull
#define OFF_COVX   33816576ull

__device__ float g_xp [T_ * B_ * G3];   // [t][b][768] bias-folded
__device__ float g_enc[B_ * T_ * H_];   // [b][t][256]
__device__ float g_mx0[2 * B_];

__device__ __forceinline__ void ffma2(float2& d, float2 a, float2 b) {
    asm("{\n\t.reg .b64 ra, rb, rd;\n\t"
        "mov.b64 ra, {%2, %3};\n\t"
        "mov.b64 rb, {%4, %5};\n\t"
        "mov.b64 rd, {%0, %1};\n\t"
        "fma.rn.f32x2 rd, ra, rb, rd;\n\t"
        "mov.b64 {%0, %1}, rd;\n\t}"
        : "+f"(d.x), "+f"(d.y)
        : "f"(a.x), "f"(a.y), "f"(b.x), "f"(b.y));
}

// ---- zero the chol_z region (134 MB) ----
__global__ void zero_kernel(float4* __restrict__ p) {
    size_t i = (size_t)blockIdx.x * blockDim.x + threadIdx.x;
    p[i] = make_float4(0.f, 0.f, 0.f, 0.f);
}

// ---- x_proj GEMM: xp[t*64+b][n] = y[b][t][:]*W_ih[n][:] + biases ----
__global__ void __launch_bounds__(256) xproj_kernel(
    const float* __restrict__ y, const float* __restrict__ W_ih,
    const float* __restrict__ b_ih, const float* __restrict__ b_hh)
{
    __shared__ float As[8][132];
    __shared__ float Bs[8][132];
    const int tid = threadIdx.x;
    const int bm = blockIdx.x & 127, bn = blockIdx.x >> 7;
    const int tx = tid & 15, ty = tid >> 4;

    float acc[8][8];
#pragma unroll
    for (int p = 0; p < 8; p++)
#pragma unroll
        for (int q = 0; q < 8; q++) acc[p][q] = 0.f;

    const int lrow = tid >> 1, lk4 = (tid & 1) * 4;
    const int gm = bm * 128 + lrow;
    const int lb = gm & 63, lt = gm >> 6;
    const float* aptr = y    + ((size_t)lb * T_ + lt) * DIN + lk4;
    const float* bptr = W_ih + (size_t)(bn * 128 + lrow) * DIN + lk4;

    for (int k0 = 0; k0 < DIN; k0 += 8) {
        float4 av = *(const float4*)(aptr + k0);
        float4 bv = *(const float4*)(bptr + k0);
        As[lk4+0][lrow]=av.x; As[lk4+1][lrow]=av.y; As[lk4+2][lrow]=av.z; As[lk4+3][lrow]=av.w;
        Bs[lk4+0][lrow]=bv.x; Bs[lk4+1][lrow]=bv.y; Bs[lk4+2][lrow]=bv.z; Bs[lk4+3][lrow]=bv.w;
        __syncthreads();
#pragma unroll
        for (int k = 0; k < 8; k++) {
            float a[8], b[8];
#pragma unroll
            for (int q = 0; q < 8; q++) a[q] = As[k][ty*8+q];
#pragma unroll
            for (int q = 0; q < 8; q++) b[q] = Bs[k][tx*8+q];
#pragma unroll
            for (int p = 0; p < 8; p++)
#pragma unroll
                for (int q = 0; q < 8; q++) acc[p][q] += a[p] * b[q];
        }
        __syncthreads();
    }
    float bq[8];
#pragma unroll
    for (int q = 0; q < 8; q++) {
        int n = bn * 128 + tx * 8 + q;
        bq[q] = b_ih[n] + (n < 2*H_ ? b_hh[n] : 0.f);   // fold b_hh for r,z gates
    }
#pragma unroll
    for (int p = 0; p < 8; p++) {
        int m = bm * 128 + ty * 8 + p;
        float* dst = g_xp + (size_t)m * G3 + bn * 128 + tx * 8;
#pragma unroll
        for (int q = 0; q < 8; q++) dst[q] = acc[p][q] + bq[q];
    }
}

// ---- GRU recurrence: 16 clusters x 8 CTAs, W_hh in registers ----
__global__ void __cluster_dims__(8, 1, 1) __launch_bounds__(256, 1)
gru_kernel(const float* __restrict__ W_hh, const float* __restrict__ b_hh)
{
    __shared__ __align__(16) float h_buf[2][4][H_];
    __shared__ float part[4][3][8][32];

    cg::cluster_group cluster = cg::this_cluster();
    const int rank = cluster.block_rank();       // 0..7 -> hidden dims [32r,32r+32)
    const int cidx = blockIdx.x >> 3;            // 0..15 -> batches [4c,4c+4)
    const int tid = threadIdx.x;
    const int j = tid & 31, kq = tid >> 5;       // kq = warp = 32-wide K chunk
    const int dim_base = rank * 32, batch_base = cidx * 4;

    float2 W2[3][16];
    const float2* Whh2 = (const float2*)W_hh;
#pragma unroll
    for (int g = 0; g < 3; g++) {
        int row = g * H_ + dim_base + j;
#pragma unroll
        for (int kk = 0; kk < 16; kk++)
            W2[g][kk] = Whh2[(size_t)row * 128 + kq * 16 + kk];
    }

    float bhn = 0.f; int rb = 0, rj = 0;
    if (tid < 128) { rb = tid >> 5; rj = tid & 31; bhn = b_hh[2*H_ + dim_base + rj]; }

    for (int i = tid; i < 4 * H_; i += 256) ((float*)h_buf[0])[i] = 0.f;
    __syncthreads();

    int s = 0;
    for (int t = 0; t < T_; t++) {
        float xr=0.f, xz=0.f, xn=0.f, hold=0.f;
        if (tid < 128) {
            const float* xpp = g_xp + (size_t)t*(B_*G3) + (size_t)(batch_base+rb)*G3 + dim_base + rj;
            xr = xpp[0]; xz = xpp[H_]; xn = xpp[2*H_];
            hold = h_buf[s][rb][dim_base + rj];
        }

        float2 acc[4][3];
#pragma unroll
        for (int b = 0; b < 4; b++)
#pragma unroll
            for (int g = 0; g < 3; g++) acc[b][g] = make_float2(0.f, 0.f);

        const float2* hb = (const float2*)h_buf[s];
#pragma unroll
        for (int kk = 0; kk < 16; kk++) {
#pragma unroll
            for (int b = 0; b < 4; b++) {
                float2 h2 = hb[b * 128 + kq * 16 + kk];   // warp-uniform -> broadcast
                ffma2(acc[b][0], W2[0][kk], h2);
                ffma2(acc[b][1], W2[1][kk], h2);
                ffma2(acc[b][2], W2[2][kk], h2);
            }
        }
#pragma unroll
        for (int b = 0; b < 4; b++)
#pragma unroll
            for (int g = 0; g < 3; g++)
                part[b][g][kq][j] = acc[b][g].x + acc[b][g].y;
        __syncthreads();

        const int ns = s ^ 1;
        if (tid < 128) {
            float sr=0.f, sz=0.f, sn=0.f;
#pragma unroll
            for (int q = 0; q < 8; q++) {
                sr += part[rb][0][q][rj];
                sz += part[rb][1][q][rj];
                sn += part[rb][2][q][rj];
            }
            float r = 1.f / (1.f + expf(-(xr + sr)));
            float z = 1.f / (1.f + expf(-(xz + sz)));
            float n = tanhf(xn + r * (sn + bhn));
            float hnew = (1.f - z) * n + z * hold;
            h_buf[ns][rb][dim_base + rj] = hnew;
            g_enc[((size_t)(batch_base + rb) * T_ + t) * H_ + dim_base + rj] = hnew;
        }

        cluster.sync();

        if (tid < 224) {  // gather 7 peers' 32-dim slices x 4 batches
            int pr = tid >> 5; pr += (pr >= rank);
            int rem = tid & 31, b = rem >> 3, v = rem & 7;
            float* lp = &h_buf[ns][b][pr * 32 + v * 4];
            const float4* src = (const float4*)cluster.map_shared_rank(lp, pr);
            *(float4*)lp = *src;
        }
        __syncthreads();
        s = ns;
    }
}

// ---- mean_x[b][0][0..1] (pre-anchor) ----
__global__ void mx0_kernel(const float* __restrict__ W_mx, const float* __restrict__ b_mx) {
    int tid = threadIdx.x;       // 128 threads
    int b = tid >> 1, ox = tid & 1;
    const float4* e = (const float4*)(g_enc + (size_t)b * (T_ * H_));
    const float4* w = (const float4*)(W_mx + ox * H_);
    float s = 0.f;
#pragma unroll 8
    for (int i = 0; i < 64; i++) {
        float4 ev = e[i], wv = w[i];
        s += ev.x*wv.x + ev.y*wv.y + ev.z*wv.z + ev.w*wv.w;
    }
    g_mx0[b * 2 + ox] = s + b_mx[ox];
}

// ---- output projections + scatter: one thread per (row, o), 96 outputs/row ----
__global__ void __launch_bounds__(256) out_kernel(
    const float* __restrict__ W_mz, const float* __restrict__ b_mz,
    const float* __restrict__ W_mx, const float* __restrict__ b_mx,
    const float* __restrict__ W_pz, const float* __restrict__ b_pz,
    const float* __restrict__ W_cx, const float* __restrict__ b_cx,
    float* __restrict__ out)
{
    int idx = blockIdx.x * 256 + threadIdx.x;       // 16384*96 threads
    int row = idx / 96, o = idx - row * 96;         // warp-aligned: 96 = 3 warps

    const float* wrow; float bias;
    if      (o < 8)  { wrow = W_mz + (size_t)o * H_;      bias = b_mz[o]; }
    else if (o < 16) { wrow = W_mx + (size_t)(o-8) * H_;  bias = b_mx[o-8]; }
    else if (o < 32) { wrow = W_pz + (size_t)(o-16) * H_; bias = b_pz[o-16]; }
    else             { wrow = W_cx + (size_t)(o-32) * H_; bias = b_cx[o-32]; }

    const float4* e4 = (const float4*)(g_enc + (size_t)row * H_);
    const float4* w4 = (const float4*)wrow;
    float s = 0.f;
#pragma unroll 8
    for (int i = 0; i < 64; i++) {
        float4 a = e4[i], w = w4[i];
        s += a.x*w.x + a.y*w.y + a.z*w.z + a.w*w.w;
    }
    s += bias;

    int b = row >> 8, t = row & 255;
    float* mean_z = out;
    float* chol   = out + OFF_CHOL;
    float* mean_x = out + OFF_MEANX;
    float* cov_x  = out + OFF_COVX;

    if (o < 8) {
        mean_z[(size_t)row * 8 + o] = s;
    } else if (o < 16) {
        int d = o - 8;
        if (d < 2) s -= g_mx0[b * 2 + d];
        mean_x[(size_t)row * 8 + d] = s;
    } else if (o < 24) {
        int d = o - 16;   // diag: softplus
        float sp = fmaxf(s, 0.f) + log1pf(expf(-fabsf(s)));
        chol[(((size_t)d * B_ + b) * T_ + t) * T_ + t] = sp;
    } else if (o < 32) {
        int d = o - 24;   // off-diag at [t, t+1]
        if (t < T_ - 1)
            chol[(((size_t)d * B_ + b) * T_ + t) * T_ + t + 1] = s;
    } else {
        cov_x[(size_t)row * 64 + (o - 32)] = s;
    }
}

extern "C" void kernel_launch(void* const* d_in, const int* in_sizes, int n_in,
                              void* d_out, int out_size) {
    const float* y    = (const float*)d_in[0];
    const float* W_ih = (const float*)d_in[1];
    const float* W_hh = (const float*)d_in[2];
    const float* b_ih = (const float*)d_in[3];
    const float* b_hh = (const float*)d_in[4];
    const float* W_mz = (const float*)d_in[5];
    const float* b_mz = (const float*)d_in[6];
    const float* W_mx = (const float*)d_in[7];
    const float* b_mx = (const float*)d_in[8];
    const float* W_pz = (const float*)d_in[9];
    const float* b_pz = (const float*)d_in[10];
    const float* W_cx = (const float*)d_in[11];
    const float* b_cx = (const float*)d_in[12];
    float* out = (float*)d_out;

    zero_kernel<<<32768, 256>>>((float4*)(out + OFF_CHOL));
    xproj_kernel<<<768, 256>>>(y, W_ih, b_ih, b_hh);
    gru_kernel<<<128, 256>>>(W_hh, b_hh);
    mx0_kernel<<<1, 128>>>(W_mx, b_mx);
    out_kernel<<<6144, 256>>>(W_mz, b_mz, W_mx, b_mx, W_pz, b_pz, W_cx, b_cx, out);
}

// round 3
// speedup vs baseline: 1.2545x; 1.2545x over previous
#include <cuda_runtime.h>
#include <cooperative_groups.h>
#include <math.h>

namespace cg = cooperative_groups;
typedef unsigned long long u64;
typedef unsigned int u32;

#define B_   64
#define T_   256
#define DIN  128
#define H_   256
#define G3   768

#define OFF_CHOL   131072ull
#define OFF_MEANX  33685504ull
#define OFF_COVX   33816576ull

__device__ float g_xp [T_ * B_ * G3];   // [t][b][768] bias-folded
__device__ float g_enc[B_ * T_ * H_];   // [b][t][256]
__device__ float g_mx0[2 * B_];

// packed fp32x2 FMA, u64 operands -> no mov packing in SASS
__device__ __forceinline__ void ffma2(u64& d, u64 a, u64 b) {
    asm("fma.rn.f32x2 %0, %1, %2, %0;" : "+l"(d) : "l"(a), "l"(b));
}
__device__ __forceinline__ float f2lo(u64 v) { return __uint_as_float((u32)v); }
__device__ __forceinline__ float f2hi(u64 v) { return __uint_as_float((u32)(v >> 32)); }

__device__ __forceinline__ u32 smem_u32(const void* p) {
    u32 a;
    asm("{ .reg .u64 t; cvta.to.shared.u64 t, %1; cvt.u32.u64 %0, t; }" : "=r"(a) : "l"(p));
    return a;
}
__device__ __forceinline__ void mbar_init(u32 mbar, u32 cnt) {
    asm volatile("mbarrier.init.shared.b64 [%0], %1;" :: "r"(mbar), "r"(cnt) : "memory");
}
__device__ __forceinline__ void mbar_arrive_local(u32 mbar) {
    asm volatile("mbarrier.arrive.release.cluster.shared::cta.b64 _, [%0];" :: "r"(mbar) : "memory");
}
__device__ __forceinline__ void mbar_arrive_peer(u32 mbar_local, u32 peer) {
    asm volatile("{\n\t.reg .b32 ra;\n\t"
                 "mapa.shared::cluster.u32 ra, %0, %1;\n\t"
                 "mbarrier.arrive.release.cluster.shared::cluster.b64 _, [ra];\n\t}"
                 :: "r"(mbar_local), "r"(peer) : "memory");
}
__device__ __forceinline__ void st_peer_f32(u32 addr_local, u32 peer, float v) {
    asm volatile("{\n\t.reg .b32 ra;\n\t"
                 "mapa.shared::cluster.u32 ra, %0, %1;\n\t"
                 "st.shared::cluster.f32 [ra], %2;\n\t}"
                 :: "r"(addr_local), "r"(peer), "f"(v) : "memory");
}
__device__ __forceinline__ void mbar_wait_cluster(u32 mbar, u32 parity) {
    u32 done;
    asm volatile("{\n\t.reg .pred p;\n\t"
                 "mbarrier.try_wait.parity.acquire.cluster.shared::cta.b64 p, [%1], %2;\n\t"
                 "selp.b32 %0, 1, 0, p;\n\t}"
                 : "=r"(done) : "r"(mbar), "r"(parity) : "memory");
    while (!done) {
        asm volatile("{\n\t.reg .pred p;\n\t"
                     "mbarrier.try_wait.parity.acquire.cluster.shared::cta.b64 p, [%1], %2, 0x989680;\n\t"
                     "selp.b32 %0, 1, 0, p;\n\t}"
                     : "=r"(done) : "r"(mbar), "r"(parity) : "memory");
    }
}
__device__ __forceinline__ float fsigmoid(float x) { return 1.f / (1.f + __expf(-x)); }
__device__ __forceinline__ float ftanh(float x)    { return 2.f / (1.f + __expf(-2.f * x)) - 1.f; }

// ---- x_proj GEMM: xp[t*64+b][n] = y[b][t][:]*W_ih[n][:] + biases ----
__global__ void __launch_bounds__(256) xproj_kernel(
    const float* __restrict__ y, const float* __restrict__ W_ih,
    const float* __restrict__ b_ih, const float* __restrict__ b_hh)
{
    __shared__ float As[8][132];
    __shared__ float Bs[8][132];
    const int tid = threadIdx.x;
    const int bm = blockIdx.x & 127, bn = blockIdx.x >> 7;
    const int tx = tid & 15, ty = tid >> 4;

    float acc[8][8];
#pragma unroll
    for (int p = 0; p < 8; p++)
#pragma unroll
        for (int q = 0; q < 8; q++) acc[p][q] = 0.f;

    const int lrow = tid >> 1, lk4 = (tid & 1) * 4;
    const int gm = bm * 128 + lrow;
    const int lb = gm & 63, lt = gm >> 6;
    const float* aptr = y    + ((size_t)lb * T_ + lt) * DIN + lk4;
    const float* bptr = W_ih + (size_t)(bn * 128 + lrow) * DIN + lk4;

    for (int k0 = 0; k0 < DIN; k0 += 8) {
        float4 av = *(const float4*)(aptr + k0);
        float4 bv = *(const float4*)(bptr + k0);
        As[lk4+0][lrow]=av.x; As[lk4+1][lrow]=av.y; As[lk4+2][lrow]=av.z; As[lk4+3][lrow]=av.w;
        Bs[lk4+0][lrow]=bv.x; Bs[lk4+1][lrow]=bv.y; Bs[lk4+2][lrow]=bv.z; Bs[lk4+3][lrow]=bv.w;
        __syncthreads();
#pragma unroll
        for (int k = 0; k < 8; k++) {
            float a[8], b[8];
#pragma unroll
            for (int q = 0; q < 8; q++) a[q] = As[k][ty*8+q];
#pragma unroll
            for (int q = 0; q < 8; q++) b[q] = Bs[k][tx*8+q];
#pragma unroll
            for (int p = 0; p < 8; p++)
#pragma unroll
                for (int q = 0; q < 8; q++) acc[p][q] += a[p] * b[q];
        }
        __syncthreads();
    }
    float bq[8];
#pragma unroll
    for (int q = 0; q < 8; q++) {
        int n = bn * 128 + tx * 8 + q;
        bq[q] = b_ih[n] + (n < 2*H_ ? b_hh[n] : 0.f);
    }
#pragma unroll
    for (int p = 0; p < 8; p++) {
        int m = bm * 128 + ty * 8 + p;
        float* dst = g_xp + (size_t)m * G3 + bn * 128 + tx * 8;
#pragma unroll
        for (int q = 0; q < 8; q++) dst[q] = acc[p][q] + bq[q];
    }
}

// ---- GRU: 16 clusters x 8 CTAs; W_hh in registers; push-model h exchange ----
__global__ void __cluster_dims__(8, 1, 1) __launch_bounds__(256, 1)
gru_kernel(const float* __restrict__ W_hh, const float* __restrict__ b_hh,
           const float* __restrict__ W_mx, const float* __restrict__ b_mx)
{
    __shared__ __align__(16) float h_buf[2][4][H_];
    __shared__ float part[4][3][8][32];
    __shared__ __align__(8) u64 mbars[2];

    cg::cluster_group cluster = cg::this_cluster();
    const int rank = cluster.block_rank();       // hidden dims [32r,32r+32)
    const int cidx = blockIdx.x >> 3;            // batches [4c,4c+4)
    const int tid = threadIdx.x;
    const int j = tid & 31, kq = tid >> 5;
    const int dim_base = rank * 32, batch_base = cidx * 4;

    // W_hh slice -> registers as packed f32x2
    u64 W2[3][16];
    const u64* Whh2 = (const u64*)W_hh;
#pragma unroll
    for (int g = 0; g < 3; g++) {
        int row = g * H_ + dim_base + j;
#pragma unroll
        for (int kk = 0; kk < 16; kk++)
            W2[g][kk] = Whh2[(size_t)row * 128 + kq * 16 + kk];
    }

    float bhn = 0.f; int rb = 0, rj = 0;
    if (tid < 128) { rb = tid >> 5; rj = tid & 31; bhn = b_hh[2*H_ + dim_base + rj]; }

    for (int i = tid; i < 4 * H_; i += 256) ((float*)h_buf[0])[i] = 0.f;
    const u32 mb[2] = { smem_u32(&mbars[0]), smem_u32(&mbars[1]) };
    if (tid == 0) { mbar_init(mb[0], 8); mbar_init(mb[1], 8); }
    __syncthreads();
    cluster.sync();   // barriers + h0 visible cluster-wide before any remote op

    for (int t = 0; t < T_; t++) {
        const int s = t & 1, ns = s ^ 1;

        // xp prefetch (global; issue before the barrier wait to hide DRAM latency)
        float xr = 0.f, xz = 0.f, xn = 0.f;
        if (tid < 128) {
            const float* xpp = g_xp + (size_t)t*(B_*G3) + (size_t)(batch_base+rb)*G3 + dim_base + rj;
            xr = xpp[0]; xz = xpp[H_]; xn = xpp[2*H_];
        }

        if (t) mbar_wait_cluster(mb[s], ((t - 1) >> 1) & 1);   // h(t-1) complete in h_buf[s]

        if (t == 1) {   // mean_x[b][0][0..1] from full h(0) in h_buf[1]
            int b = kq >> 1, d = kq & 1;
            float sum = 0.f;
#pragma unroll
            for (int i = 0; i < 8; i++)
                sum += h_buf[1][b][j * 8 + i] * W_mx[d * H_ + j * 8 + i];
#pragma unroll
            for (int o = 16; o > 0; o >>= 1) sum += __shfl_xor_sync(0xffffffffu, sum, o);
            if (j == 0) g_mx0[(batch_base + b) * 2 + d] = sum + b_mx[d];
        }

        float hold = 0.f;
        if (tid < 128) hold = h_buf[s][rb][dim_base + rj];

        // matvec: 4 batches x 3 gates, 32-wide K chunk per thread, FFMA2
        u64 acc[4][3];
#pragma unroll
        for (int b = 0; b < 4; b++)
#pragma unroll
            for (int g = 0; g < 3; g++) acc[b][g] = 0ull;

        const u64* hb = (const u64*)h_buf[s];
#pragma unroll
        for (int kk = 0; kk < 16; kk++) {
#pragma unroll
            for (int b = 0; b < 4; b++) {
                u64 h2 = hb[b * 128 + kq * 16 + kk];
                ffma2(acc[b][0], W2[0][kk], h2);
                ffma2(acc[b][1], W2[1][kk], h2);
                ffma2(acc[b][2], W2[2][kk], h2);
            }
        }
#pragma unroll
        for (int b = 0; b < 4; b++)
#pragma unroll
            for (int g = 0; g < 3; g++)
                part[b][g][kq][j] = f2lo(acc[b][g]) + f2hi(acc[b][g]);
        __syncthreads();

        if (tid < 128) {
            float sr = 0.f, sz = 0.f, sn = 0.f;
#pragma unroll
            for (int q = 0; q < 8; q++) {
                sr += part[rb][0][q][rj];
                sz += part[rb][1][q][rj];
                sn += part[rb][2][q][rj];
            }
            float r = fsigmoid(xr + sr);
            float z = fsigmoid(xz + sz);
            float n = ftanh(xn + r * (sn + bhn));
            float hnew = (1.f - z) * n + z * hold;
            float* lp = &h_buf[ns][rb][dim_base + rj];
            *lp = hnew;
            g_enc[((size_t)(batch_base + rb) * T_ + t) * H_ + dim_base + rj] = hnew;
            if (t < T_ - 1) {
                u32 la = smem_u32(lp);
#pragma unroll
                for (int p = 0; p < 8; p++)
                    if (p != rank) st_peer_f32(la, p, hnew);
            }
        }
        __syncthreads();   // all pushes issued before the release-arrive

        if (t < T_ - 1 && tid < 8) {
            if (tid == rank) mbar_arrive_local(mb[ns]);
            else             mbar_arrive_peer(mb[ns], tid);
        }
    }
    cluster.sync();
}

// ---- output projections + chol materialization (sole chol writer) ----
// block = 16 rows (one b, 16 t's). thread: 2 rows x 3 outputs. K in 4 chunks of 64.
__global__ void __launch_bounds__(256) out_kernel(
    const float* __restrict__ W_mz, const float* __restrict__ b_mz,
    const float* __restrict__ W_mx, const float* __restrict__ b_mx,
    const float* __restrict__ W_pz, const float* __restrict__ b_pz,
    const float* __restrict__ W_cx, const float* __restrict__ b_cx,
    float* __restrict__ out)
{
    __shared__ float es[16 * 256];     // enc tile
    __shared__ float Ws[64 * 97];      // W chunk, transposed [k][o], padded
    __shared__ float bs[96];

    const int tid = threadIdx.x;
    const int chunk = blockIdx.x;               // 1024 blocks
    const int row0 = chunk * 16;
    const int b = row0 >> 8, t0 = row0 & 255;

    const int rp = tid >> 5;                    // row pair 0..7
    const int og = tid & 31;                    // output triple 0..31
    const int r0 = rp * 2, obase = og * 3;

    // chol zero-fill for this block's (8 d) x (16 t) rows, 256 cols each
    float* chol = out + OFF_CHOL;
    {
        float4 z4 = make_float4(0.f, 0.f, 0.f, 0.f);
#pragma unroll
        for (int d = 0; d < 8; d++) {
            float4* base = (float4*)(chol + (((size_t)d * B_ + b) * T_ + t0) * T_);
            for (int i = tid; i < 1024; i += 256) base[i] = z4;   // 16 rows x 64 f4
        }
    }

    if (tid < 96) {
        float bv;
        if      (tid < 8)  bv = b_mz[tid];
        else if (tid < 16) bv = b_mx[tid - 8];
        else if (tid < 32) bv = b_pz[tid - 16];
        else               bv = b_cx[tid - 32];
        bs[tid] = bv;
    }
    {   // enc tile load: 16x256 floats, coalesced
        const float4* src = (const float4*)(g_enc + (size_t)row0 * H_);
        float4* dst = (float4*)es;
#pragma unroll
        for (int i = 0; i < 4; i++) dst[tid + 256 * i] = src[tid + 256 * i];
    }

    float acc[2][3];
#pragma unroll
    for (int r = 0; r < 2; r++)
#pragma unroll
        for (int q = 0; q < 3; q++) acc[r][q] = 0.f;

    for (int kc = 0; kc < 4; kc++) {
        __syncthreads();
        // load W chunk transposed: rows o in [0,96), k in [kc*64, kc*64+64)
        for (int i = tid; i < 96 * 16; i += 256) {
            int o = i >> 4, f4 = i & 15;
            const float* wrow;
            if      (o < 8)  wrow = W_mz + (size_t)o * H_;
            else if (o < 16) wrow = W_mx + (size_t)(o - 8) * H_;
            else if (o < 32) wrow = W_pz + (size_t)(o - 16) * H_;
            else             wrow = W_cx + (size_t)(o - 32) * H_;
            float4 v = ((const float4*)wrow)[kc * 16 + f4];
            Ws[(f4 * 4 + 0) * 97 + o] = v.x;
            Ws[(f4 * 4 + 1) * 97 + o] = v.y;
            Ws[(f4 * 4 + 2) * 97 + o] = v.z;
            Ws[(f4 * 4 + 3) * 97 + o] = v.w;
        }
        __syncthreads();
#pragma unroll 8
        for (int k = 0; k < 64; k++) {
            float a0 = es[r0 * 256 + kc * 64 + k];
            float a1 = es[(r0 + 1) * 256 + kc * 64 + k];
            float w0 = Ws[k * 97 + obase];
            float w1 = Ws[k * 97 + obase + 1];
            float w2 = Ws[k * 97 + obase + 2];
            acc[0][0] += a0 * w0; acc[0][1] += a0 * w1; acc[0][2] += a0 * w2;
            acc[1][0] += a1 * w0; acc[1][1] += a1 * w1; acc[1][2] += a1 * w2;
        }
    }
    __syncthreads();   // zeros done before value scatter (zero phase long finished, but order-safe)

    float* mean_z = out;
    float* mean_x = out + OFF_MEANX;
    float* cov_x  = out + OFF_COVX;

#pragma unroll
    for (int r = 0; r < 2; r++) {
        int row = row0 + r0 + r;
        int t = row & 255;
#pragma unroll
        for (int q = 0; q < 3; q++) {
            int o = obase + q;
            float s = acc[r][q] + bs[o];
            if (o < 8) {
                mean_z[(size_t)row * 8 + o] = s;
            } else if (o < 16) {
                int d = o - 8;
                if (d < 2) s -= g_mx0[b * 2 + d];
                mean_x[(size_t)row * 8 + d] = s;
            } else if (o < 24) {
                int d = o - 16;
                float sp = fmaxf(s, 0.f) + log1pf(__expf(-fabsf(s)));
                chol[(((size_t)d * B_ + b) * T_ + t) * T_ + t] = sp;
            } else if (o < 32) {
                int d = o - 24;
                if (t < T_ - 1)
                    chol[(((size_t)d * B_ + b) * T_ + t) * T_ + t + 1] = s;
            } else {
                cov_x[(size_t)row * 64 + (o - 32)] = s;
            }
        }
    }
}

extern "C" void kernel_launch(void* const* d_in, const int* in_sizes, int n_in,
                              void* d_out, int out_size) {
    const float* y    = (const float*)d_in[0];
    const float* W_ih = (const float*)d_in[1];
    const float* W_hh = (const float*)d_in[2];
    const float* b_ih = (const float*)d_in[3];
    const float* b_hh = (const float*)d_in[4];
    const float* W_mz = (const float*)d_in[5];
    const float* b_mz = (const float*)d_in[6];
    const float* W_mx = (const float*)d_in[7];
    const float* b_mx = (const float*)d_in[8];
    const float* W_pz = (const float*)d_in[9];
    const float* b_pz = (const float*)d_in[10];
    const float* W_cx = (const float*)d_in[11];
    const float* b_cx = (const float*)d_in[12];
    float* out = (float*)d_out;

    xproj_kernel<<<768, 256>>>(y, W_ih, b_ih, b_hh);
    gru_kernel<<<128, 256>>>(W_hh, b_hh, W_mx, b_mx);
    out_kernel<<<1024, 256>>>(W_mz, b_mz, W_mx, b_mx, W_pz, b_pz, W_cx, b_cx, out);
}